// round 15
// baseline (speedup 1.0000x reference)
#include <cuda_runtime.h>
#include <stdint.h>

// ==================== problem constants ====================
#define NN    4264      // all_node_num
#define BB    256       // batch
#define NGRP  8
#define GSZ   533       // NN / NGRP
#define KMAX  64        // ELL row capacity (mean deg ~15; 64 unreachable)
#define NWRP  17        // warps per gibbs CTA (544 threads)
#define CPB   2         // chains per CTA
#define SMAX  16        // precomputed-rand capacity (dataset sample_num = 10)

#define ELLT_TOTAL ((size_t)NGRP * KMAX * GSZ + 64)

// ==================== device scratch (no allocs allowed) ====================
__device__ int2  g_Jt [ELLT_TOTAL];          // original-slot ELL (build output)
__device__ int2  g_Jt2[ELLT_TOTAL];          // nnz-sorted ELL (gibbs input)
__device__ int   g_inv[NN];                  // node -> g*GSZ + j
__device__ int   g_nnzt[NGRP * 544];         // per (g, j-orig) nnz
__device__ int   g_perm[NGRP * 544];         // sorted slot jp -> j orig
__device__ int   g_node[NGRP * 544];         // sorted slot jp -> node id
__device__ int   g_kmaxw[NGRP * NWRP];       // per (g, gibbs-warp) max nnz (sorted)
__device__ uint2 g_gkeys[256 * NGRP];        // [sweep][group] -> key pair
// precomputed randoms r in sorted-slot, chain-pair-interleaved layout:
// g_R[(((s*NGRP+g)*(BB/2)+bp)*544 + jp)*2 + c]
__device__ float g_R[(size_t)SMAX * NGRP * (BB / 2) * 544 * 2];

// ==================== threefry2x32 (exact JAX rounds) ====================
__device__ __forceinline__ uint2 threefry(uint32_t k0, uint32_t k1,
                                          uint32_t x0, uint32_t x1) {
    uint32_t ks2 = k0 ^ k1 ^ 0x1BD11BDAu;
    x0 += k0; x1 += k1;
#define TF_RND(r) { x0 += x1; x1 = (x1 << (r)) | (x1 >> (32 - (r))); x1 ^= x0; }
    TF_RND(13) TF_RND(15) TF_RND(26) TF_RND(6)
    x0 += k1;  x1 += ks2 + 1u;
    TF_RND(17) TF_RND(29) TF_RND(16) TF_RND(24)
    x0 += ks2; x1 += k0 + 2u;
    TF_RND(13) TF_RND(15) TF_RND(26) TF_RND(6)
    x0 += k0;  x1 += k1 + 3u;
    TF_RND(17) TF_RND(29) TF_RND(16) TF_RND(24)
    x0 += k1;  x1 += ks2 + 4u;
    TF_RND(13) TF_RND(15) TF_RND(26) TF_RND(6)
    x0 += ks2; x1 += k0 + 5u;
#undef TF_RND
    return make_uint2(x0, x1);
}

__device__ __forceinline__ float draw_to_r(uint32_t bits) {
    float u = __uint_as_float((bits >> 9) | 0x3f800000u) - 1.0f;
    return u * 2.0f - 1.0f;
}

// ==================== XLA EmitFastTanh (bit-replication) ====================
__device__ __forceinline__ float tanh_xla(float x) {
    float ax = fabsf(x);
    float xc = fmaxf(fminf(x, 7.90531110763549805f), -7.90531110763549805f);
    float x2 = xc * xc;
    float p = __fmaf_rn(x2, -2.76076847742355e-16f, 2.00018790482477e-13f);
    p = __fmaf_rn(x2, p, -8.60467152213735e-11f);
    p = __fmaf_rn(x2, p,  5.12229709037114e-08f);
    p = __fmaf_rn(x2, p,  1.48572235717979e-05f);
    p = __fmaf_rn(x2, p,  6.37261928875436e-04f);
    p = __fmaf_rn(x2, p,  4.89352455891786e-03f);
    p = xc * p;
    float q = __fmaf_rn(x2, 1.19825839466702e-06f, 1.18534705686654e-04f);
    q = __fmaf_rn(x2, q, 2.26843463243900e-03f);
    q = __fmaf_rn(x2, q, 4.89352518554385e-03f);
    float r = __fdiv_rn(p, q);
    return (ax < 0.0004f) ? x : r;
}

__device__ __forceinline__ int clamp_sn(int sn) {
    if (sn < 0) sn = 0;
    if (sn > 256) sn = 256;
    return sn;
}

// ==================== kernel 0: prep (inverse map + small zeroing) =========
__global__ void prep(const int* __restrict__ groups) {
    int i = blockIdx.x * blockDim.x + threadIdx.x;
    if (i < NN) g_inv[groups[i]] = i;
    if (i < NGRP * 544) g_perm[i] = 0;
}

// ==================== kernel 1: build original-slot ELL =====================
// One warp per row; float4 scan; ascending-column order preserved.
__global__ void build_ellt(const float* __restrict__ J) {
    int row = blockIdx.x * (blockDim.x >> 5) + (threadIdx.x >> 5);
    if (row >= NN) return;
    const int lane = threadIdx.x & 31;
    const int p = g_inv[row];
    const int g = p / GSZ, j = p % GSZ;
    const float4* Jr4 = (const float4*)(J + (size_t)row * NN);   // NN % 4 == 0

    int base = 0;
    const int NQ = NN / 4;                     // 1066 float4s
    for (int it = 0; it < (NQ + 31) / 32; it++) {
        int q = it * 32 + lane;
        float4 v = make_float4(0.f, 0.f, 0.f, 0.f);
        if (q < NQ) v = Jr4[q];
        int cnt = (v.x != 0.f) + (v.y != 0.f) + (v.z != 0.f) + (v.w != 0.f);
        int incl = cnt;
#pragma unroll
        for (int off = 1; off < 32; off <<= 1) {
            int n = __shfl_up_sync(0xffffffffu, incl, off);
            if (lane >= off) incl += n;
        }
        int pos = base + (incl - cnt);
        int c0 = q * 4;
        if (v.x != 0.f && pos < KMAX) { g_Jt[(size_t)(g * KMAX + pos) * GSZ + j] = make_int2(__float_as_int(v.x), c0 + 0); pos++; }
        if (v.y != 0.f && pos < KMAX) { g_Jt[(size_t)(g * KMAX + pos) * GSZ + j] = make_int2(__float_as_int(v.y), c0 + 1); pos++; }
        if (v.z != 0.f && pos < KMAX) { g_Jt[(size_t)(g * KMAX + pos) * GSZ + j] = make_int2(__float_as_int(v.z), c0 + 2); pos++; }
        if (v.w != 0.f && pos < KMAX) { g_Jt[(size_t)(g * KMAX + pos) * GSZ + j] = make_int2(__float_as_int(v.w), c0 + 3); pos++; }
        base += __shfl_sync(0xffffffffu, incl, 31);
    }
    if (lane == 0) g_nnzt[g * 544 + j] = (base < KMAX) ? base : KMAX;
}

// ==================== kernel 2: deterministic nnz-descending rank sort =====
__global__ void sortperm(const int* __restrict__ groups) {
    const int g = blockIdx.x;            // 8 blocks, 544 threads
    const int tid = threadIdx.x;
    __shared__ int nnz_s[544];
    __shared__ int perm_s[544];
    nnz_s[tid] = (tid < GSZ) ? g_nnzt[g * 544 + tid] : -1;
    __syncthreads();
    if (tid < GSZ) {
        const int n = nnz_s[tid];
        int rank = 0;
        for (int j2 = 0; j2 < GSZ; j2++) {
            int n2 = nnz_s[j2];
            rank += (n2 > n) || (n2 == n && j2 < tid);
        }
        perm_s[rank] = tid;
    }
    __syncthreads();
    if (tid < GSZ) {
        const int j = perm_s[tid];
        g_perm[g * 544 + tid] = j;
        g_node[g * 544 + tid] = groups[g * GSZ + j];
    } else {
        g_node[g * 544 + tid] = 0;
    }
    // warp-max nnz in sorted order = nnz of warp's first (largest) slot
    if ((tid & 31) == 0 && tid < GSZ)
        g_kmaxw[g * NWRP + (tid >> 5)] = nnz_s[perm_s[tid]];
}

// ==================== kernel 3: repack ELL columns into sorted order =======
__global__ void repack() {
    size_t i = (size_t)blockIdx.x * blockDim.x + threadIdx.x;
    const size_t total = (size_t)NGRP * KMAX * GSZ;
    if (i < total) {
        int jp = (int)(i % GSZ);
        int gk = (int)(i / GSZ);
        int g  = gk / KMAX;
        int k  = gk % KMAX;
        int j  = g_perm[g * 544 + jp];
        int2 e = make_int2(0, 0);
        if (k < g_nnzt[g * 544 + j])
            e = g_Jt[(size_t)gk * GSZ + j];
        g_Jt2[i] = e;
    } else if (i < ELLT_TOTAL) {
        g_Jt2[i] = make_int2(0, 0);        // pad for inactive-lane reads
    }
}

// ==================== kernel 4: key schedule ====================
__global__ void keygen(const int* __restrict__ sn_ptr) {
    int s = blockIdx.x * blockDim.x + threadIdx.x;
    int sn = clamp_sn(*sn_ptr);
    if (s < sn) {
        uint2 ik = threefry(0u, 42u, 0u, (uint32_t)s);   // foldlike split
#pragma unroll
        for (int g = 0; g < NGRP; g++)
            g_gkeys[s * NGRP + g] = threefry(ik.x, ik.y, 0u, (uint32_t)g);
    }
}

// ==================== kernel 5: precompute all randoms (full occupancy) ====
__global__ __launch_bounds__(544) void randgen(const int* __restrict__ sn_ptr) {
    const int sn = clamp_sn(*sn_ptr);
    const int blk = blockIdx.x;                   // s*NGRP*(BB/2) + g*(BB/2) + bp
    const int s   = blk / (NGRP * (BB / 2));
    if (s >= sn || s >= SMAX) return;
    const int rem = blk % (NGRP * (BB / 2));
    const int g   = rem / (BB / 2);
    const int bp  = rem % (BB / 2);
    const int jp  = threadIdx.x;
    const int j   = g_perm[g * 544 + jp];
    const uint2 kk = g_gkeys[s * NGRP + g];
    const uint32_t f0 = (uint32_t)((2 * bp) * GSZ + j);
    const uint2 oA = threefry(kk.x, kk.y, 0u, f0);
    const uint2 oB = threefry(kk.x, kk.y, 0u, f0 + GSZ);
    const size_t base = (((size_t)(s * NGRP + g) * (BB / 2) + bp) * 544 + jp) * 2;
    g_R[base]     = draw_to_r(oA.x ^ oA.y);
    g_R[base + 1] = draw_to_r(oB.x ^ oB.y);
}

// ==================== kernel 6: Gibbs sweeps, 2 chains per CTA =============
__global__ __launch_bounds__(544) void gibbs(
    const float* __restrict__ m_in, const float* __restrict__ H,
    const int* __restrict__ sn_ptr, float* __restrict__ out)
{
    __shared__ float2 ms[NN];                 // .x = chain b0, .y = chain b1
    const int bp = blockIdx.x;
    const int b0 = bp * CPB, b1 = b0 + 1;
    const int tid = threadIdx.x;
    const int w = tid >> 5;

    for (int i = tid; i < NN; i += blockDim.x)
        ms[i] = make_float2(m_in[(size_t)b0 * NN + i], m_in[(size_t)b1 * NN + i]);
    const int sn = clamp_sn(*sn_ptr);
    const bool active = (tid < GSZ);

    // per-thread / per-warp invariants (sorted-slot domain)
    int   nodeR[NGRP];
    float hR[NGRP];
    int   kmw[NGRP];
#pragma unroll
    for (int g = 0; g < NGRP; g++) {
        int node = g_node[g * 544 + tid];     // 0 for dummy lanes
        nodeR[g] = node;
        hR[g]    = H[node];
        kmw[g]   = g_kmaxw[g * NWRP + w];     // warp-uniform inner bound
    }
    __syncthreads();

    if (sn <= SMAX) {
        for (int s = 0; s < sn; s++) {
#pragma unroll
            for (int g = 0; g < NGRP; g++) {
                // precomputed randoms: one coalesced LDG.64, issued early
                const float2 rr = *(const float2*)(g_R +
                    (((size_t)(s * NGRP + g) * (BB / 2) + bp) * 544 + tid) * 2);

                const int2* __restrict__ ep = g_Jt2 + (size_t)(g * KMAX) * GSZ + tid;
                const int km = kmw[g];
                float acc0 = 0.0f, acc1 = 0.0f;
#pragma unroll 4
                for (int k = 0; k < km; k++) {
                    int2 e = ep[(size_t)k * GSZ];
                    float2 mv = ms[e.y];                    // one LDS.64, 2 chains
                    float v = __int_as_float(e.x);
                    acc0 = __fmaf_rn(v, mv.x, acc0);
                    acc1 = __fmaf_rn(v, mv.y, acc1);
                }
                const float d0 = tanh_xla(acc0 + hR[g]) - rr.x;
                const float d1 = tanh_xla(acc1 + hR[g]) - rr.y;
                const float n0 = (d0 > 0.0f) ? 1.0f : ((d0 < 0.0f) ? -1.0f : 0.0f);
                const float n1 = (d1 > 0.0f) ? 1.0f : ((d1 < 0.0f) ? -1.0f : 0.0f);

                __syncthreads();              // all reads of ms precede write
                if (active) ms[nodeR[g]] = make_float2(n0, n1);
                __syncthreads();
            }
        }
    } else {
        // fallback (sn > SMAX): inline PRNG, same math
        for (int s = 0; s < sn; s++) {
#pragma unroll
            for (int g = 0; g < NGRP; g++) {
                const int j = g_perm[g * 544 + tid];
                const uint2 kk = g_gkeys[s * NGRP + g];
                const uint32_t f0 = (uint32_t)(b0 * GSZ + j);
                const uint2 oA = threefry(kk.x, kk.y, 0u, f0);
                const uint2 oB = threefry(kk.x, kk.y, 0u, f0 + GSZ);
                const float r0 = draw_to_r(oA.x ^ oA.y);
                const float r1 = draw_to_r(oB.x ^ oB.y);
                const int2* __restrict__ ep = g_Jt2 + (size_t)(g * KMAX) * GSZ + tid;
                const int km = kmw[g];
                float acc0 = 0.0f, acc1 = 0.0f;
                for (int k = 0; k < km; k++) {
                    int2 e = ep[(size_t)k * GSZ];
                    float2 mv = ms[e.y];
                    float v = __int_as_float(e.x);
                    acc0 = __fmaf_rn(v, mv.x, acc0);
                    acc1 = __fmaf_rn(v, mv.y, acc1);
                }
                const float d0 = tanh_xla(acc0 + hR[g]) - r0;
                const float d1 = tanh_xla(acc1 + hR[g]) - r1;
                const float n0 = (d0 > 0.0f) ? 1.0f : ((d0 < 0.0f) ? -1.0f : 0.0f);
                const float n1 = (d1 > 0.0f) ? 1.0f : ((d1 < 0.0f) ? -1.0f : 0.0f);
                __syncthreads();
                if (active) ms[nodeR[g]] = make_float2(n0, n1);
                __syncthreads();
            }
        }
    }

    for (int i = tid; i < NN; i += blockDim.x) {
        float2 v = ms[i];
        out[(size_t)b0 * NN + i] = v.x;
        out[(size_t)b1 * NN + i] = v.y;
    }
}

// ==================== launch ====================
extern "C" void kernel_launch(void* const* d_in, const int* in_sizes, int n_in,
                              void* d_out, int out_size) {
    const float* m      = (const float*)d_in[0];
    const float* J      = (const float*)d_in[1];
    const float* H      = (const float*)d_in[2];
    const int*   groups = (const int*)d_in[3];
    const int*   sn     = (const int*)d_in[4];
    float* out          = (float*)d_out;
    (void)in_sizes; (void)n_in; (void)out_size;

    prep<<<(NN + 255) / 256, 256>>>(groups);
    build_ellt<<<(NN + 3) / 4, 128>>>(J);           // warp per row, float4 scan
    sortperm<<<NGRP, 544>>>(groups);
    repack<<<(int)((ELLT_TOTAL + 255) / 256), 256>>>();
    keygen<<<1, 256>>>(sn);
    randgen<<<SMAX * NGRP * (BB / 2), 544>>>(sn);
    gibbs<<<BB / CPB, 544>>>(m, H, sn, out);
}

// round 16
// speedup vs baseline: 1.7304x; 1.7304x over previous
#include <cuda_runtime.h>
#include <stdint.h>

// ==================== problem constants ====================
#define NN    4264      // all_node_num
#define BB    256       // batch
#define NGRP  8
#define GSZ   533       // NN / NGRP
#define KMAX  64        // ELL row capacity (mean deg ~15; 64 unreachable)
#define CPB   2         // chains per CTA
#define NT    512       // gibbs threads (16 warps, 4 per SMSP)
#define JSTR  544       // sorted-ELL row stride (pad slots 533..543 are zeros)
#define NEXTRA (GSZ - NT)   // 21 secondary slots, handled by warp 15

#define ELLT_TOTAL  ((size_t)NGRP * KMAX * GSZ + 64)   // original-slot ELL
#define ELLT2_TOTAL ((size_t)NGRP * KMAX * JSTR)       // sorted, padded ELL

// ==================== device scratch (no allocs allowed) ====================
__device__ int2  g_Jt [ELLT_TOTAL];          // original-slot ELL (build output)
__device__ int2  g_Jt2[ELLT2_TOTAL];         // nnz-sorted ELL (gibbs input)
__device__ int   g_inv[NN];                  // node -> g*GSZ + j
__device__ int   g_nnzt[NGRP * JSTR];        // per (g, j-orig) nnz
__device__ int   g_perm[NGRP * JSTR];        // sorted slot jp -> j orig (pads=0)
__device__ int   g_node[NGRP * JSTR];        // sorted slot jp -> node id (pads=0)
__device__ int   g_kmaxw[NGRP * 32];         // [g*32+w] warp max nnz; [g*32+16]=extras
__device__ uint2 g_gkeys[256 * NGRP];        // [sweep][group] -> key pair

// ==================== threefry2x32 (exact JAX rounds) ====================
__device__ __forceinline__ uint2 threefry(uint32_t k0, uint32_t k1,
                                          uint32_t x0, uint32_t x1) {
    uint32_t ks2 = k0 ^ k1 ^ 0x1BD11BDAu;
    x0 += k0; x1 += k1;
#define TF_RND(r) { x0 += x1; x1 = (x1 << (r)) | (x1 >> (32 - (r))); x1 ^= x0; }
    TF_RND(13) TF_RND(15) TF_RND(26) TF_RND(6)
    x0 += k1;  x1 += ks2 + 1u;
    TF_RND(17) TF_RND(29) TF_RND(16) TF_RND(24)
    x0 += ks2; x1 += k0 + 2u;
    TF_RND(13) TF_RND(15) TF_RND(26) TF_RND(6)
    x0 += k0;  x1 += k1 + 3u;
    TF_RND(17) TF_RND(29) TF_RND(16) TF_RND(24)
    x0 += k1;  x1 += ks2 + 4u;
    TF_RND(13) TF_RND(15) TF_RND(26) TF_RND(6)
    x0 += ks2; x1 += k0 + 5u;
#undef TF_RND
    return make_uint2(x0, x1);
}

__device__ __forceinline__ float draw_to_r(uint32_t bits) {
    float u = __uint_as_float((bits >> 9) | 0x3f800000u) - 1.0f;
    return u * 2.0f - 1.0f;
}

// ==================== XLA EmitFastTanh (bit-replication) ====================
__device__ __forceinline__ float tanh_xla(float x) {
    float ax = fabsf(x);
    float xc = fmaxf(fminf(x, 7.90531110763549805f), -7.90531110763549805f);
    float x2 = xc * xc;
    float p = __fmaf_rn(x2, -2.76076847742355e-16f, 2.00018790482477e-13f);
    p = __fmaf_rn(x2, p, -8.60467152213735e-11f);
    p = __fmaf_rn(x2, p,  5.12229709037114e-08f);
    p = __fmaf_rn(x2, p,  1.48572235717979e-05f);
    p = __fmaf_rn(x2, p,  6.37261928875436e-04f);
    p = __fmaf_rn(x2, p,  4.89352455891786e-03f);
    p = xc * p;
    float q = __fmaf_rn(x2, 1.19825839466702e-06f, 1.18534705686654e-04f);
    q = __fmaf_rn(x2, q, 2.26843463243900e-03f);
    q = __fmaf_rn(x2, q, 4.89352518554385e-03f);
    float r = __fdiv_rn(p, q);
    return (ax < 0.0004f) ? x : r;
}

__device__ __forceinline__ int clamp_sn(int sn) {
    if (sn < 0) sn = 0;
    if (sn > 256) sn = 256;
    return sn;
}

__device__ __forceinline__ float sgn(float d) {
    return (d > 0.0f) ? 1.0f : ((d < 0.0f) ? -1.0f : 0.0f);
}

// ==================== kernel 0: prep (inverse map + pad zeroing) ===========
__global__ void prep(const int* __restrict__ groups) {
    int i = blockIdx.x * blockDim.x + threadIdx.x;
    if (i < NN) g_inv[groups[i]] = i;
    if (i < NGRP * JSTR) g_perm[i] = 0;
}

// ==================== kernel 1: build original-slot ELL =====================
// One warp per row; float4 scan; ascending-column order preserved.
__global__ void build_ellt(const float* __restrict__ J) {
    int row = blockIdx.x * (blockDim.x >> 5) + (threadIdx.x >> 5);
    if (row >= NN) return;
    const int lane = threadIdx.x & 31;
    const int p = g_inv[row];
    const int g = p / GSZ, j = p % GSZ;
    const float4* Jr4 = (const float4*)(J + (size_t)row * NN);   // NN % 4 == 0

    int base = 0;
    const int NQ = NN / 4;                     // 1066 float4s
    for (int it = 0; it < (NQ + 31) / 32; it++) {
        int q = it * 32 + lane;
        float4 v = make_float4(0.f, 0.f, 0.f, 0.f);
        if (q < NQ) v = Jr4[q];
        int cnt = (v.x != 0.f) + (v.y != 0.f) + (v.z != 0.f) + (v.w != 0.f);
        int incl = cnt;
#pragma unroll
        for (int off = 1; off < 32; off <<= 1) {
            int n = __shfl_up_sync(0xffffffffu, incl, off);
            if (lane >= off) incl += n;
        }
        int pos = base + (incl - cnt);
        int c0 = q * 4;
        if (v.x != 0.f && pos < KMAX) { g_Jt[(size_t)(g * KMAX + pos) * GSZ + j] = make_int2(__float_as_int(v.x), c0 + 0); pos++; }
        if (v.y != 0.f && pos < KMAX) { g_Jt[(size_t)(g * KMAX + pos) * GSZ + j] = make_int2(__float_as_int(v.y), c0 + 1); pos++; }
        if (v.z != 0.f && pos < KMAX) { g_Jt[(size_t)(g * KMAX + pos) * GSZ + j] = make_int2(__float_as_int(v.z), c0 + 2); pos++; }
        if (v.w != 0.f && pos < KMAX) { g_Jt[(size_t)(g * KMAX + pos) * GSZ + j] = make_int2(__float_as_int(v.w), c0 + 3); pos++; }
        base += __shfl_sync(0xffffffffu, incl, 31);
    }
    if (lane == 0) g_nnzt[g * JSTR + j] = (base < KMAX) ? base : KMAX;
}

// ==================== kernel 2: deterministic nnz-descending rank sort =====
__global__ void sortperm(const int* __restrict__ groups) {
    const int g = blockIdx.x;            // 8 blocks, 544 threads
    const int tid = threadIdx.x;
    __shared__ int nnz_s[JSTR];
    __shared__ int perm_s[JSTR];
    nnz_s[tid] = (tid < GSZ) ? g_nnzt[g * JSTR + tid] : -1;
    __syncthreads();
    if (tid < GSZ) {
        const int n = nnz_s[tid];
        int rank = 0;
        for (int j2 = 0; j2 < GSZ; j2++) {
            int n2 = nnz_s[j2];
            rank += (n2 > n) || (n2 == n && j2 < tid);
        }
        perm_s[rank] = tid;
    }
    __syncthreads();
    if (tid < GSZ) {
        const int j = perm_s[tid];
        g_perm[g * JSTR + tid] = j;
        g_node[g * JSTR + tid] = groups[g * GSZ + j];
    } else {
        g_node[g * JSTR + tid] = 0;      // pad slots
    }
    // per-warp max nnz in sorted order = nnz of warp's first (largest) slot
    if ((tid & 31) == 0 && tid < NT)
        g_kmaxw[g * 32 + (tid >> 5)] = nnz_s[perm_s[tid]];
    if (tid == NT)                        // extras (slots 512..532) max
        g_kmaxw[g * 32 + 16] = nnz_s[perm_s[NT]];
}

// ==================== kernel 3: repack ELL into sorted, padded layout ======
__global__ void repack() {
    size_t i = (size_t)blockIdx.x * blockDim.x + threadIdx.x;
    if (i >= ELLT2_TOTAL) return;
    int jp = (int)(i % JSTR);
    int gk = (int)(i / JSTR);
    int g  = gk / KMAX;
    int k  = gk % KMAX;
    int2 e = make_int2(0, 0);
    if (jp < GSZ) {
        int j = g_perm[g * JSTR + jp];
        if (k < g_nnzt[g * JSTR + j])
            e = g_Jt[(size_t)gk * GSZ + j];
    }
    g_Jt2[i] = e;
}

// ==================== kernel 4: key schedule ====================
__global__ void keygen(const int* __restrict__ sn_ptr) {
    int s = blockIdx.x * blockDim.x + threadIdx.x;
    int sn = clamp_sn(*sn_ptr);
    if (s < sn) {
        uint2 ik = threefry(0u, 42u, 0u, (uint32_t)s);   // foldlike split
#pragma unroll
        for (int g = 0; g < NGRP; g++)
            g_gkeys[s * NGRP + g] = threefry(ik.x, ik.y, 0u, (uint32_t)g);
    }
}

// ==================== kernel 5: Gibbs sweeps, 2 chains per CTA, 16 warps ===
__global__ __launch_bounds__(NT) void gibbs(
    const float* __restrict__ m_in, const float* __restrict__ H,
    const int* __restrict__ sn_ptr, float* __restrict__ out)
{
    __shared__ float2 ms[NN];                 // .x = chain b0, .y = chain b1
    const int b0 = blockIdx.x * CPB;
    const int tid = threadIdx.x;
    const int w = tid >> 5;
    const bool w15 = (w == 15);               // warp 15 carries the 21 extras
    const bool has2 = (tid >= 480) && (tid < 480 + NEXTRA);

    for (int i = tid; i < NN; i += NT)
        ms[i] = make_float2(m_in[(size_t)b0 * NN + i],
                            m_in[(size_t)(b0 + 1) * NN + i]);
    const int sn = clamp_sn(*sn_ptr);

    // per-thread / per-warp invariants (sorted-slot domain)
    int nodeR[NGRP];  float hR[NGRP];  int kmw[NGRP];  uint32_t fR[NGRP];
    int node2R[NGRP]; float h2R[NGRP]; int km2;        uint32_t f2R[NGRP];
    km2 = g_kmaxw[16];  // placeholder init
#pragma unroll
    for (int g = 0; g < NGRP; g++) {
        nodeR[g] = g_node[g * JSTR + tid];
        hR[g]    = H[nodeR[g]];
        kmw[g]   = g_kmaxw[g * 32 + w];
        fR[g]    = (uint32_t)(b0 * GSZ + g_perm[g * JSTR + tid]);
        if (w15) {
            const int jp2 = NT + (tid - 480);     // 512..543 (>=533 are pads)
            node2R[g] = g_node[g * JSTR + jp2];
            h2R[g]    = H[node2R[g]];
            f2R[g]    = (uint32_t)(b0 * GSZ + g_perm[g * JSTR + jp2]);
        }
    }
    const int km2w = g_kmaxw[16];   // extras bound lives at g*32+16; max over g below
    // use per-g extras bound:
    int km2R[NGRP];
#pragma unroll
    for (int g = 0; g < NGRP; g++) km2R[g] = g_kmaxw[g * 32 + 16];
    (void)km2; (void)km2w;
    __syncthreads();

    for (int s = 0; s < sn; s++) {
#pragma unroll
        for (int g = 0; g < NGRP; g++) {
            const uint2 kk = g_gkeys[s * NGRP + g];
            // primary PRNG: two dependent ALU chains overlap the gathers
            const uint2 oA = threefry(kk.x, kk.y, 0u, fR[g]);
            const uint2 oB = threefry(kk.x, kk.y, 0u, fR[g] + GSZ);
            const float r0 = draw_to_r(oA.x ^ oA.y);
            const float r1 = draw_to_r(oB.x ^ oB.y);

            // primary gather: coalesced sorted ELL, one entry feeds 2 chains
            const int2* __restrict__ ep = g_Jt2 + (size_t)(g * KMAX) * JSTR + tid;
            const int km = kmw[g];
            float acc0 = 0.0f, acc1 = 0.0f;
            for (int k = 0; k < km; k++) {
                int2 e = ep[(size_t)k * JSTR];
                float2 mv = ms[e.y];                    // one LDS.64, 2 chains
                float v = __int_as_float(e.x);
                acc0 = __fmaf_rn(v, mv.x, acc0);
                acc1 = __fmaf_rn(v, mv.y, acc1);
            }
            const float n0 = sgn(tanh_xla(acc0 + hR[g]) - r0);
            const float n1 = sgn(tanh_xla(acc1 + hR[g]) - r1);

            // secondary slots (warp 15 only; lightest slots, lightest warp)
            float m0 = 0.0f, m1 = 0.0f;
            if (w15) {
                const uint2 oC = threefry(kk.x, kk.y, 0u, f2R[g]);
                const uint2 oD = threefry(kk.x, kk.y, 0u, f2R[g] + GSZ);
                const int2* __restrict__ e2 =
                    g_Jt2 + (size_t)(g * KMAX) * JSTR + (NT + (tid - 480));
                float a0 = 0.0f, a1 = 0.0f;
                const int k2 = km2R[g];
                for (int k = 0; k < k2; k++) {
                    int2 e = e2[(size_t)k * JSTR];
                    float2 mv = ms[e.y];
                    float v = __int_as_float(e.x);
                    a0 = __fmaf_rn(v, mv.x, a0);
                    a1 = __fmaf_rn(v, mv.y, a1);
                }
                m0 = sgn(tanh_xla(a0 + h2R[g]) - draw_to_r(oC.x ^ oC.y));
                m1 = sgn(tanh_xla(a1 + h2R[g]) - draw_to_r(oD.x ^ oD.y));
            }

            __syncthreads();                  // all reads of ms precede writes
            ms[nodeR[g]] = make_float2(n0, n1);
            if (has2) ms[node2R[g]] = make_float2(m0, m1);
            __syncthreads();
        }
    }

    for (int i = tid; i < NN; i += NT) {
        float2 v = ms[i];
        out[(size_t)b0 * NN + i]       = v.x;
        out[(size_t)(b0 + 1) * NN + i] = v.y;
    }
}

// ==================== launch ====================
extern "C" void kernel_launch(void* const* d_in, const int* in_sizes, int n_in,
                              void* d_out, int out_size) {
    const float* m      = (const float*)d_in[0];
    const float* J      = (const float*)d_in[1];
    const float* H      = (const float*)d_in[2];
    const int*   groups = (const int*)d_in[3];
    const int*   sn     = (const int*)d_in[4];
    float* out          = (float*)d_out;
    (void)in_sizes; (void)n_in; (void)out_size;

    prep<<<(NN + 255) / 256, 256>>>(groups);
    build_ellt<<<(NN + 3) / 4, 128>>>(J);           // warp per row, float4 scan
    sortperm<<<NGRP, JSTR>>>(groups);
    repack<<<(int)((ELLT2_TOTAL + 255) / 256), 256>>>();
    keygen<<<1, 256>>>(sn);
    gibbs<<<BB / CPB, NT>>>(m, H, sn, out);
}